// round 1
// baseline (speedup 1.0000x reference)
#include <cuda_runtime.h>
#include <cuda_bf16.h>

#define FULL_MASK 0xffffffffu

__global__ __launch_bounds__(256) void anfis_kernel(
    const float* __restrict__ x,
    const float* __restrict__ mu,
    const float* __restrict__ sg,
    const float* __restrict__ ta,
    const float* __restrict__ tb,
    const float* __restrict__ tc,
    const float* __restrict__ td,
    const float* __restrict__ mfmix,
    const float* __restrict__ tnw,
    const float* __restrict__ conseq,
    const int*   __restrict__ ridx,
    float* __restrict__ out0,   // [B]
    float* __restrict__ outN,   // [B,128]
    float* __restrict__ outM,   // [B,14]
    int B)
{
    const int tid    = blockIdx.x * blockDim.x + threadIdx.x;
    const int warp   = tid >> 5;
    const int lane   = tid & 31;
    const int nwarps = (gridDim.x * blockDim.x) >> 5;

    // ---- per-lane rules: r = lane + 32*k (k=0..3) ----
    float cq[4][8];
    int   mask[4];
#pragma unroll
    for (int k = 0; k < 4; ++k) {
        const int r = lane + 32 * k;
        const float4* cp = reinterpret_cast<const float4*>(conseq + r * 8);
        float4 c0 = cp[0], c1 = cp[1];
        cq[k][0] = c0.x; cq[k][1] = c0.y; cq[k][2] = c0.z; cq[k][3] = c0.w;
        cq[k][4] = c1.x; cq[k][5] = c1.y; cq[k][6] = c1.z; cq[k][7] = c1.w;
        int m = 0;
#pragma unroll
        for (int f = 0; f < 7; ++f) m |= (ridx[r * 7 + f] & 1) << f;
        mask[k] = m;
    }

    const float alpha = 1.f / (1.f + __expf(-mfmix[0]));
    const float w     = 1.f / (1.f + __expf(-tnw[0]));

    // ---- element-invariant membership params (lanes 0..13: j=lane, f=j>>1, set=j&1) ----
    float muv = 0.f, i2s = 0.f, av = 0.f, bv = 0.f, cv = 0.f, dv = 0.f;
    float iba = 0.f, idc = 0.f;
    if (lane < 14) {
        muv = mu[lane];
        float s = fmaxf(sg[lane], 1e-6f);
        i2s = 1.f / (2.f * s * s);
        float p0 = ta[lane], p1 = tb[lane], p2 = tc[lane], p3 = td[lane];
        float t;
        t = fminf(p0, p1); p1 = fmaxf(p0, p1); p0 = t;
        t = fminf(p2, p3); p3 = fmaxf(p2, p3); p2 = t;
        t = fminf(p0, p2); p2 = fmaxf(p0, p2); p0 = t;
        t = fminf(p1, p3); p3 = fmaxf(p1, p3); p1 = t;
        t = fminf(p1, p2); p2 = fmaxf(p1, p2); p1 = t;
        av = p0; bv = p1; cv = p2; dv = p3;
        iba = 1.f / (p1 - p0 + 1e-6f);
        idc = 1.f / (p3 - p2 + 1e-6f);
    }

    for (int b = warp; b < B; b += nwarps) {
        // ---- membership (lanes 0..13) ----
        float xf = 0.f, memv = 0.f;
        if (lane < 14) {
            xf = __ldg(&x[b * 7 + (lane >> 1)]);
            float t     = xf - muv;
            float gauss = __expf(-t * t * i2s);
            float left  = fminf(fmaxf((xf - av) * iba, 0.f), 1.f);
            float right = fminf(fmaxf((dv - xf) * idc, 0.f), 1.f);
            float flat  = (xf >= bv && xf <= cv) ? 1.f : 0.f;
            float trap  = fmaxf(fminf(left, right), flat);
            memv = trap + alpha * (gauss - trap);   // alpha*g + (1-alpha)*trap
            outM[b * 14 + lane] = memv;
        }

        // ---- broadcast memberships + x to all lanes ----
        float mA[7], mB[7], xr[7];
#pragma unroll
        for (int f = 0; f < 7; ++f) {
            mA[f] = __shfl_sync(FULL_MASK, memv, 2 * f);
            mB[f] = __shfl_sync(FULL_MASK, memv, 2 * f + 1);
            xr[f] = __shfl_sync(FULL_MASK, xf,   2 * f);
        }

        // ---- firing strength for this lane's 4 rules ----
        float fir[4];
#pragma unroll
        for (int k = 0; k < 4; ++k) {
            const int m = mask[k];
            float p  = 1.f;
            float mn = 2.f;  // memberships are in [0,1]
#pragma unroll
            for (int f = 0; f < 7; ++f) {
                float g = (m & (1 << f)) ? mB[f] : mA[f];
                p  *= g;
                mn  = fminf(mn, g);
            }
            fir[k] = mn + w * (p - mn);   // w*prod + (1-w)*min
        }

        // ---- normalization ----
        float s = (fir[0] + fir[1]) + (fir[2] + fir[3]);
#pragma unroll
        for (int off = 16; off > 0; off >>= 1) s += __shfl_xor_sync(FULL_MASK, s, off);
        const float inv = __fdividef(1.f, s + 1e-8f);

        // ---- norm_firing store + weighted consequent ----
        float acc = 0.f;
#pragma unroll
        for (int k = 0; k < 4; ++k) {
            const float nf = fir[k] * inv;
            outN[(long)b * 128 + 32 * k + lane] = nf;
            float ro = cq[k][0];
#pragma unroll
            for (int f = 0; f < 7; ++f) ro = fmaf(cq[k][f + 1], xr[f], ro);
            acc = fmaf(nf, ro, acc);
        }
#pragma unroll
        for (int off = 16; off > 0; off >>= 1) acc += __shfl_xor_sync(FULL_MASK, acc, off);
        if (lane == 0) out0[b] = acc;
    }
}

extern "C" void kernel_launch(void* const* d_in, const int* in_sizes, int n_in,
                              void* d_out, int out_size) {
    const float* x      = (const float*)d_in[0];
    const float* mu     = (const float*)d_in[1];
    const float* sg     = (const float*)d_in[2];
    const float* ta     = (const float*)d_in[3];
    const float* tb     = (const float*)d_in[4];
    const float* tc     = (const float*)d_in[5];
    const float* td     = (const float*)d_in[6];
    const float* mfmix  = (const float*)d_in[7];
    const float* tnw    = (const float*)d_in[8];
    const float* conseq = (const float*)d_in[9];
    const int*   ridx   = (const int*)d_in[10];

    const int B = in_sizes[0] / 7;

    float* o  = (float*)d_out;
    float* oN = o + B;             // norm_firing [B,128]
    float* oM = o + B + (long)B * 128;  // mem [B,14]

    anfis_kernel<<<1024, 256>>>(x, mu, sg, ta, tb, tc, td, mfmix, tnw,
                                conseq, ridx, o, oN, oM, B);
}

// round 2
// speedup vs baseline: 1.2674x; 1.2674x over previous
#include <cuda_runtime.h>
#include <cuda_bf16.h>

#define FULL_MASK 0xffffffffu

__global__ __launch_bounds__(256) void anfis_kernel(
    const float* __restrict__ x,
    const float* __restrict__ mu,
    const float* __restrict__ sg,
    const float* __restrict__ ta,
    const float* __restrict__ tb,
    const float* __restrict__ tc,
    const float* __restrict__ td,
    const float* __restrict__ mfmix,
    const float* __restrict__ tnw,
    const float* __restrict__ conseq,
    const int*   __restrict__ ridx,
    float* __restrict__ out0,   // [B]
    float* __restrict__ outN,   // [B,128]
    float* __restrict__ outM,   // [B,14]
    int B)
{
    const int tid    = blockIdx.x * blockDim.x + threadIdx.x;
    const int warp   = tid >> 5;
    const int lane   = tid & 31;
    const int nwarps = (gridDim.x * blockDim.x) >> 5;

    // ---- per-lane rules: r = lane + 32*k (k=0..3) ----
    float cq[4][8];
    int   mask[4];
#pragma unroll
    for (int k = 0; k < 4; ++k) {
        const int r = lane + 32 * k;
        const float4* cp = reinterpret_cast<const float4*>(conseq + r * 8);
        float4 c0 = cp[0], c1 = cp[1];
        cq[k][0] = c0.x; cq[k][1] = c0.y; cq[k][2] = c0.z; cq[k][3] = c0.w;
        cq[k][4] = c1.x; cq[k][5] = c1.y; cq[k][6] = c1.z; cq[k][7] = c1.w;
        int m = 0;
#pragma unroll
        for (int f = 0; f < 7; ++f) m |= (ridx[r * 7 + f] & 1) << f;
        mask[k] = m;
    }

    // Structure check: the 4 masks of this lane must agree on features 2..6.
    const int diff = (mask[0]^mask[1]) | (mask[0]^mask[2]) | (mask[0]^mask[3]);
    const bool fast = __all_sync(FULL_MASK, (diff & 0x7C) == 0);

    // Precomputed shuffle sources for the 5 shared features (mem index = 2f + set)
    int src2 = 4  + ((mask[0] >> 2) & 1);
    int src3 = 6  + ((mask[0] >> 3) & 1);
    int src4 = 8  + ((mask[0] >> 4) & 1);
    int src5 = 10 + ((mask[0] >> 5) & 1);
    int src6 = 12 + ((mask[0] >> 6) & 1);

    const float alpha = 1.f / (1.f + __expf(-mfmix[0]));
    const float w     = 1.f / (1.f + __expf(-tnw[0]));

    // ---- element-invariant membership params (lanes 0..13: f=lane>>1, set=lane&1) ----
    float muv = 0.f, i2s = 0.f, av = 0.f, bv = 0.f, cv = 0.f, dv = 0.f;
    float iba = 0.f, idc = 0.f;
    if (lane < 14) {
        muv = mu[lane];
        float s = fmaxf(sg[lane], 1e-6f);
        i2s = 1.f / (2.f * s * s);
        float p0 = ta[lane], p1 = tb[lane], p2 = tc[lane], p3 = td[lane];
        float t;
        t = fminf(p0, p1); p1 = fmaxf(p0, p1); p0 = t;
        t = fminf(p2, p3); p3 = fmaxf(p2, p3); p2 = t;
        t = fminf(p0, p2); p2 = fmaxf(p0, p2); p0 = t;
        t = fminf(p1, p3); p3 = fmaxf(p1, p3); p1 = t;
        t = fminf(p1, p2); p2 = fmaxf(p1, p2); p1 = t;
        av = p0; bv = p1; cv = p2; dv = p3;
        iba = 1.f / (p1 - p0 + 1e-6f);
        idc = 1.f / (p3 - p2 + 1e-6f);
    }

    if (fast) {
        for (int b = warp; b < B; b += nwarps) {
            const float* xb = x + b * 7;
            // broadcast x via L1 (uniform address across warp)
            float xv0 = __ldg(xb+0), xv1 = __ldg(xb+1), xv2 = __ldg(xb+2),
                  xv3 = __ldg(xb+3), xv4 = __ldg(xb+4), xv5 = __ldg(xb+5),
                  xv6 = __ldg(xb+6);

            // ---- membership (lanes 0..13) ----
            float memv = 0.f;
            if (lane < 14) {
                float xf = __ldg(xb + (lane >> 1));
                float t     = xf - muv;
                float gauss = __expf(-t * t * i2s);
                float left  = fminf(fmaxf((xf - av) * iba, 0.f), 1.f);
                float right = fminf(fmaxf((dv - xf) * idc, 0.f), 1.f);
                float flat  = (xf >= bv && xf <= cv) ? 1.f : 0.f;
                float trap  = fmaxf(fminf(left, right), flat);
                memv = trap + alpha * (gauss - trap);
                outM[b * 14 + lane] = memv;
            }

            // ---- gather this lane's 5 shared-feature memberships directly ----
            float g2 = __shfl_sync(FULL_MASK, memv, src2);
            float g3 = __shfl_sync(FULL_MASK, memv, src3);
            float g4 = __shfl_sync(FULL_MASK, memv, src4);
            float g5 = __shfl_sync(FULL_MASK, memv, src5);
            float g6 = __shfl_sync(FULL_MASK, memv, src6);
            // features 0,1 (both sets) for the pair combos
            float mA0 = __shfl_sync(FULL_MASK, memv, 0);
            float mB0 = __shfl_sync(FULL_MASK, memv, 1);
            float mA1 = __shfl_sync(FULL_MASK, memv, 2);
            float mB1 = __shfl_sync(FULL_MASK, memv, 3);

            float pp = ((g2 * g3) * (g4 * g5)) * g6;
            float pm = fminf(fminf(fminf(g2, g3), fminf(g4, g5)), g6);

            // ---- firing + fir*ro for this lane's 4 rules ----
            float fir[4];
            float s1 = 0.f, s2 = 0.f;
#pragma unroll
            for (int k = 0; k < 4; ++k) {
                const int m = mask[k];
                float u = (m & 1) ? mB0 : mA0;   // feature 0
                float v = (m & 2) ? mB1 : mA1;   // feature 1
                float p  = pp * (u * v);
                float mn = fminf(pm, fminf(u, v));
                float f  = mn + w * (p - mn);
                fir[k] = f;
                float ro = cq[k][0];
                ro = fmaf(cq[k][1], xv0, ro);
                ro = fmaf(cq[k][2], xv1, ro);
                ro = fmaf(cq[k][3], xv2, ro);
                ro = fmaf(cq[k][4], xv3, ro);
                ro = fmaf(cq[k][5], xv4, ro);
                ro = fmaf(cq[k][6], xv5, ro);
                ro = fmaf(cq[k][7], xv6, ro);
                s1 += f;
                s2 = fmaf(f, ro, s2);
            }

            // ---- fused dual butterfly reduction ----
#pragma unroll
            for (int off = 16; off > 0; off >>= 1) {
                s1 += __shfl_xor_sync(FULL_MASK, s1, off);
                s2 += __shfl_xor_sync(FULL_MASK, s2, off);
            }
            const float inv = __fdividef(1.f, s1 + 1e-8f);

            float* nb = outN + (long)b * 128 + lane;
            nb[0]  = fir[0] * inv;
            nb[32] = fir[1] * inv;
            nb[64] = fir[2] * inv;
            nb[96] = fir[3] * inv;
            if (lane == 0) out0[b] = s2 * inv;
        }
    } else {
        // ---- generic fallback (structure assumption violated) ----
        for (int b = warp; b < B; b += nwarps) {
            const float* xb = x + b * 7;
            float xv0 = __ldg(xb+0), xv1 = __ldg(xb+1), xv2 = __ldg(xb+2),
                  xv3 = __ldg(xb+3), xv4 = __ldg(xb+4), xv5 = __ldg(xb+5),
                  xv6 = __ldg(xb+6);
            float memv = 0.f;
            if (lane < 14) {
                float xf = __ldg(xb + (lane >> 1));
                float t     = xf - muv;
                float gauss = __expf(-t * t * i2s);
                float left  = fminf(fmaxf((xf - av) * iba, 0.f), 1.f);
                float right = fminf(fmaxf((dv - xf) * idc, 0.f), 1.f);
                float flat  = (xf >= bv && xf <= cv) ? 1.f : 0.f;
                float trap  = fmaxf(fminf(left, right), flat);
                memv = trap + alpha * (gauss - trap);
                outM[b * 14 + lane] = memv;
            }
            float mA[7], mB[7];
#pragma unroll
            for (int f = 0; f < 7; ++f) {
                mA[f] = __shfl_sync(FULL_MASK, memv, 2 * f);
                mB[f] = __shfl_sync(FULL_MASK, memv, 2 * f + 1);
            }
            float fir[4], s1 = 0.f, s2 = 0.f;
#pragma unroll
            for (int k = 0; k < 4; ++k) {
                const int m = mask[k];
                float p = 1.f, mn = 2.f;
#pragma unroll
                for (int f = 0; f < 7; ++f) {
                    float g = (m & (1 << f)) ? mB[f] : mA[f];
                    p *= g; mn = fminf(mn, g);
                }
                float fk = mn + w * (p - mn);
                fir[k] = fk;
                float ro = cq[k][0];
                ro = fmaf(cq[k][1], xv0, ro);
                ro = fmaf(cq[k][2], xv1, ro);
                ro = fmaf(cq[k][3], xv2, ro);
                ro = fmaf(cq[k][4], xv3, ro);
                ro = fmaf(cq[k][5], xv4, ro);
                ro = fmaf(cq[k][6], xv5, ro);
                ro = fmaf(cq[k][7], xv6, ro);
                s1 += fk;
                s2 = fmaf(fk, ro, s2);
            }
#pragma unroll
            for (int off = 16; off > 0; off >>= 1) {
                s1 += __shfl_xor_sync(FULL_MASK, s1, off);
                s2 += __shfl_xor_sync(FULL_MASK, s2, off);
            }
            const float inv = __fdividef(1.f, s1 + 1e-8f);
            float* nb = outN + (long)b * 128 + lane;
            nb[0]  = fir[0] * inv;
            nb[32] = fir[1] * inv;
            nb[64] = fir[2] * inv;
            nb[96] = fir[3] * inv;
            if (lane == 0) out0[b] = s2 * inv;
        }
    }
}

extern "C" void kernel_launch(void* const* d_in, const int* in_sizes, int n_in,
                              void* d_out, int out_size) {
    const float* x      = (const float*)d_in[0];
    const float* mu     = (const float*)d_in[1];
    const float* sg     = (const float*)d_in[2];
    const float* ta     = (const float*)d_in[3];
    const float* tb     = (const float*)d_in[4];
    const float* tc     = (const float*)d_in[5];
    const float* td     = (const float*)d_in[6];
    const float* mfmix  = (const float*)d_in[7];
    const float* tnw    = (const float*)d_in[8];
    const float* conseq = (const float*)d_in[9];
    const int*   ridx   = (const int*)d_in[10];

    const int B = in_sizes[0] / 7;

    float* o  = (float*)d_out;
    float* oN = o + B;                  // norm_firing [B,128]
    float* oM = o + B + (long)B * 128;  // mem [B,14]

    anfis_kernel<<<1024, 256>>>(x, mu, sg, ta, tb, tc, td, mfmix, tnw,
                                conseq, ridx, o, oN, oM, B);
}